// round 9
// baseline (speedup 1.0000x reference)
#include <cuda_runtime.h>
#include <cuda_bf16.h>
#include <cstdint>
#include <math.h>

typedef __nv_bfloat16 bf16;

#define BB   2
#define SS   2048
#define HID  2048
#define HQ   16
#define HKV  4
#define MM   (BB*SS)          // 4096
#define QDIM 2048
#define KVDIM 512

// ---------------- scratch ----------------
__device__ __align__(16) bf16 g_h_hi[MM*HID];
__device__ __align__(16) bf16 g_h_lo[MM*HID];
__device__ __align__(16) bf16 g_wq_hi[QDIM*HID];
__device__ __align__(16) bf16 g_wq_lo[QDIM*HID];
__device__ __align__(16) bf16 g_wk_hi[KVDIM*HID];
__device__ __align__(16) bf16 g_wk_lo[KVDIM*HID];
__device__ __align__(16) bf16 g_wv_hi[KVDIM*HID];
__device__ __align__(16) bf16 g_wv_lo[KVDIM*HID];
__device__ __align__(16) bf16 g_wo_hi[HID*QDIM];
__device__ __align__(16) bf16 g_wo_lo[HID*QDIM];
__device__ __align__(16) float g_q[MM*QDIM];
__device__ __align__(16) float g_k[MM*KVDIM];
__device__ __align__(16) float g_v[MM*KVDIM];
__device__ __align__(16) bf16 g_qh[MM*QDIM];
__device__ __align__(16) bf16 g_ql[MM*QDIM];
__device__ __align__(16) bf16 g_kh[MM*KVDIM];
__device__ __align__(16) bf16 g_kl[MM*KVDIM];
__device__ __align__(16) bf16 g_att_hi[MM*QDIM];
__device__ __align__(16) bf16 g_att_lo[MM*QDIM];

// ---------------- helpers ----------------
__device__ __forceinline__ uint32_t smem_u32(const void* p) {
    uint32_t a;
    asm("{ .reg .u64 t; cvta.to.shared.u64 t, %1; cvt.u32.u64 %0, t; }" : "=r"(a) : "l"(p));
    return a;
}
__device__ __forceinline__ void cp16(uint32_t dst, const void* src) {
    asm volatile("cp.async.cg.shared.global [%0], [%1], 16;" :: "r"(dst), "l"(src));
}
#define CP_COMMIT() asm volatile("cp.async.commit_group;" ::: "memory")
#define CP_WAIT(n)  asm volatile("cp.async.wait_group %0;" :: "n"(n) : "memory")

// volatile + memory clobber: pinned in program order; never rematerialized
__device__ __forceinline__ uint32_t lds32(uint32_t a) {
    uint32_t v;
    asm volatile("ld.shared.b32 %0, [%1];" : "=r"(v) : "r"(a) : "memory");
    return v;
}
__device__ __forceinline__ void mma16816(float* d, const uint32_t* a, const uint32_t* b) {
    asm volatile("mma.sync.aligned.m16n8k16.row.col.f32.bf16.bf16.f32 "
        "{%0,%1,%2,%3}, {%4,%5,%6,%7}, {%8,%9}, {%0,%1,%2,%3};"
        : "+f"(d[0]), "+f"(d[1]), "+f"(d[2]), "+f"(d[3])
        : "r"(a[0]), "r"(a[1]), "r"(a[2]), "r"(a[3]), "r"(b[0]), "r"(b[1]));
}

// ---------------------------------------------------------------------------
// RMSNorm -> bf16 hi/lo (validated)
// ---------------------------------------------------------------------------
__global__ void rmsnorm_kernel(const float* __restrict__ x,
                               const float* __restrict__ w,
                               bf16* __restrict__ ohi, bf16* __restrict__ olo) {
    int row = blockIdx.x;
    int tid = threadIdx.x;
    const float4* xr = (const float4*)(x + (size_t)row * HID);
    float4 a = xr[tid];
    float4 b = xr[tid + 256];
    float ss = a.x*a.x + a.y*a.y + a.z*a.z + a.w*a.w
             + b.x*b.x + b.y*b.y + b.z*b.z + b.w*b.w;
    #pragma unroll
    for (int off = 16; off > 0; off >>= 1)
        ss += __shfl_xor_sync(0xffffffffu, ss, off);
    __shared__ float sred[8];
    __shared__ float sinv;
    if ((tid & 31) == 0) sred[tid >> 5] = ss;
    __syncthreads();
    if (tid == 0) {
        float t = 0.f;
        #pragma unroll
        for (int i = 0; i < 8; i++) t += sred[i];
        sinv = rsqrtf(t / (float)HID + 1e-6f);
    }
    __syncthreads();
    float inv = sinv;
    const float4* wr = (const float4*)w;
    float4 wa = wr[tid], wb = wr[tid + 256];
    float va[8] = { a.x*inv*wa.x, a.y*inv*wa.y, a.z*inv*wa.z, a.w*inv*wa.w,
                    b.x*inv*wb.x, b.y*inv*wb.y, b.z*inv*wb.z, b.w*inv*wb.w };
    size_t base0 = (size_t)row * HID + tid*4;
    size_t base1 = (size_t)row * HID + (tid+256)*4;
    #pragma unroll
    for (int i = 0; i < 4; i++) {
        bf16 h0 = __float2bfloat16(va[i]);
        ohi[base0+i] = h0;
        olo[base0+i] = __float2bfloat16(va[i] - __bfloat162float(h0));
        bf16 h1 = __float2bfloat16(va[4+i]);
        ohi[base1+i] = h1;
        olo[base1+i] = __float2bfloat16(va[4+i] - __bfloat162float(h1));
    }
}

// ---------------------------------------------------------------------------
// split fp32 -> bf16 hi/lo (validated)
// ---------------------------------------------------------------------------
__global__ void split_kernel(const float* __restrict__ in, bf16* __restrict__ hi,
                             bf16* __restrict__ lo, int n4) {
    int i = blockIdx.x * 256 + threadIdx.x;
    if (i >= n4) return;
    float4 v = ((const float4*)in)[i];
    bf16 h0 = __float2bfloat16(v.x), h1 = __float2bfloat16(v.y);
    bf16 h2 = __float2bfloat16(v.z), h3 = __float2bfloat16(v.w);
    __nv_bfloat162 hh0; hh0.x = h0; hh0.y = h1;
    __nv_bfloat162 hh1; hh1.x = h2; hh1.y = h3;
    __nv_bfloat162 ll0, ll1;
    ll0.x = __float2bfloat16(v.x - __bfloat162float(h0));
    ll0.y = __float2bfloat16(v.y - __bfloat162float(h1));
    ll1.x = __float2bfloat16(v.z - __bfloat162float(h2));
    ll1.y = __float2bfloat16(v.w - __bfloat162float(h3));
    ((__nv_bfloat162*)hi)[i*2+0] = hh0;
    ((__nv_bfloat162*)hi)[i*2+1] = hh1;
    ((__nv_bfloat162*)lo)[i*2+0] = ll0;
    ((__nv_bfloat162*)lo)[i*2+1] = ll1;
}

// ---------------------------------------------------------------------------
// HMMA GEMM (NT): validated patterns, now 512 threads (16 warps, 4/SMSP).
// Warp grid 4(m) x 4(n), warp tile 32x32. Tile 128x128, K-chunk 64,
// cp.async double-buffered. smem 131072 B.
// ---------------------------------------------------------------------------
__global__ __launch_bounds__(512, 1)
void gemm_mma(const bf16* __restrict__ Ah, const bf16* __restrict__ Al,
              const bf16* __restrict__ Bh, const bf16* __restrict__ Bl,
              const float* __restrict__ bias, float* __restrict__ Cf, int N) {
    extern __shared__ __align__(128) char sm[];
    uint32_t sb = smem_u32(sm);
    int tid = threadIdx.x;
    int w = tid >> 5, lane = tid & 31, g = lane >> 2, tig = lane & 3;
    int wm = w & 3, wn = w >> 2;
    int brow = blockIdx.y * 128, bcol = blockIdx.x * 128;

    float acc[2][4][4];
    #pragma unroll
    for (int a = 0; a < 2; a++)
        #pragma unroll
        for (int b = 0; b < 4; b++)
            #pragma unroll
            for (int c = 0; c < 4; c++) acc[a][b][c] = 0.f;

    auto load_stage = [&](int s, int ck) {
        #pragma unroll
        for (int mat = 0; mat < 4; mat++) {
            const bf16* base = (mat == 0) ? Ah : (mat == 1) ? Al : (mat == 2) ? Bh : Bl;
            int ro = (mat < 2) ? brow : bcol;
            #pragma unroll
            for (int i = 0; i < 2; i++) {
                int id = i*512 + tid;
                int r = id >> 3, c = id & 7;
                cp16(sb + s*65536 + mat*16384 + r*128 + (((uint32_t)c*16) ^ ((uint32_t)(r&7)*16)),
                     base + (size_t)(ro + r)*2048 + ck*64 + c*8);
            }
        }
    };

    load_stage(0, 0);
    CP_COMMIT();

    for (int ck = 0; ck < 32; ck++) {
        if (ck + 1 < 32) { load_stage((ck+1)&1, ck+1); CP_COMMIT(); CP_WAIT(1); }
        else             { CP_WAIT(0); }
        __syncthreads();
        uint32_t tb = sb + (ck&1)*65536;
        uint32_t swz = (uint32_t)g*16;
        #pragma unroll
        for (int ks = 0; ks < 4; ks++) {
            uint32_t o0 = (uint32_t)(32*ks + 4*tig);
            uint32_t ah[2][4], al[2][4];
            #pragma unroll
            for (int mb = 0; mb < 2; mb++) {
                uint32_t r0 = (uint32_t)(wm*32 + mb*16 + g)*128;
                uint32_t r1 = r0 + 8*128;
                ah[mb][0] = lds32(tb + r0 + (o0^swz));
                ah[mb][1] = lds32(tb + r1 + (o0^swz));
                ah[mb][2] = lds32(tb + r0 + ((o0+16)^swz));
                ah[mb][3] = lds32(tb + r1 + ((o0+16)^swz));
                al[mb][0] = lds32(tb + 16384 + r0 + (o0^swz));
                al[mb][1] = lds32(tb + 16384 + r1 + (o0^swz));
                al[mb][2] = lds32(tb + 16384 + r0 + ((o0+16)^swz));
                al[mb][3] = lds32(tb + 16384 + r1 + ((o0+16)^swz));
            }
            uint32_t bh[4][2], bl[4][2];
            #pragma unroll
            for (int nb = 0; nb < 4; nb++) {
                uint32_t rB = (uint32_t)(wn*32 + nb*8 + g)*128;
                bh[nb][0] = lds32(tb + 2*16384 + rB + (o0^swz));
                bh[nb][1] = lds32(tb + 2*16384 + rB + ((o0+16)^swz));
                bl[nb][0] = lds32(tb + 3*16384 + rB + (o0^swz));
                bl[nb][1] = lds32(tb + 3*16384 + rB + ((o0+16)^swz));
            }
            #pragma unroll
            for (int mb = 0; mb < 2; mb++)
                #pragma unroll
                for (int nb = 0; nb < 4; nb++) {
                    mma16816(acc[mb][nb], ah[mb], bh[nb]);
                    mma16816(acc[mb][nb], ah[mb], bl[nb]);
                    mma16816(acc[mb][nb], al[mb], bh[nb]);
                }
        }
        __syncthreads();
    }

    #pragma unroll
    for (int mb = 0; mb < 2; mb++) {
        #pragma unroll
        for (int half = 0; half < 2; half++) {
            int row = brow + wm*32 + mb*16 + g + 8*half;
            #pragma unroll
            for (int nb = 0; nb < 4; nb++) {
                int col = bcol + wn*32 + nb*8 + 2*tig;
                float v0 = acc[mb][nb][2*half];
                float v1 = acc[mb][nb][2*half+1];
                if (bias) { v0 += bias[col]; v1 += bias[col+1]; }
                *(float2*)(Cf + (size_t)row * N + col) = make_float2(v0, v1);
            }
        }
    }
}

// ---------------------------------------------------------------------------
// RoPE: fp32 in -> bf16 hi/lo out (validated)
// ---------------------------------------------------------------------------
__global__ void rope_split_kernel(const float* __restrict__ t,
                                  bf16* __restrict__ oh, bf16* __restrict__ ol,
                                  int nHeads, int total) {
    int idx = blockIdx.x * blockDim.x + threadIdx.x;
    if (idx >= total) return;
    int j = idx & 63;
    int h = (idx >> 6) % nHeads;
    int s = (idx / (64 * nHeads)) % SS;
    int b = idx / (64 * nHeads * SS);
    float inv_freq = expf(-((float)(2*j) / 128.f) * logf(10000.f));
    float ang = (float)s * inv_freq;
    float c, sn;
    sincosf(ang, &sn, &c);
    size_t base = ((size_t)(b*SS + s) * nHeads + h) * 128;
    float a0 = t[base + j];
    float a1 = t[base + j + 64];
    float r0 = a0 * c - a1 * sn;
    float r1 = a1 * c + a0 * sn;
    bf16 h0 = __float2bfloat16(r0);
    oh[base + j] = h0;
    ol[base + j] = __float2bfloat16(r0 - __bfloat162float(h0));
    bf16 h1 = __float2bfloat16(r1);
    oh[base + j + 64] = h1;
    ol[base + j + 64] = __float2bfloat16(r1 - __bfloat162float(h1));
}

// ---------------------------------------------------------------------------
// Attention: HMMA S = QK^T (3-term hi/lo) + register softmax + fp32 PV.
// (validated in round 8; epilogue now emits bf16 hi/lo directly)
// ---------------------------------------------------------------------------
#define KH_OFF 32768
#define VS_OFF 65536
#define PS_OFF 99328
#define ATTN_SMEM 116736

__global__ __launch_bounds__(128)
void attn_smma(const bf16* __restrict__ qh, const bf16* __restrict__ ql,
               const bf16* __restrict__ kh, const bf16* __restrict__ kl,
               const float* __restrict__ v,
               bf16* __restrict__ oh, bf16* __restrict__ ol) {
    extern __shared__ __align__(128) char sm[];
    uint32_t sb = smem_u32(sm);
    int tid = threadIdx.x, w = tid >> 5, lane = tid & 31, g = lane >> 2, tig = lane & 3;
    int qt = gridDim.x - 1 - blockIdx.x;
    int hq = blockIdx.y, b = blockIdx.z, gkv = hq >> 2;
    int q0 = qt * 64;
    uint32_t swz = (uint32_t)g*16;
    int row0 = w*16 + g, row1 = row0 + 8;

    // ---- stage Q hi/lo into dedicated regions 0/1 ----
    #pragma unroll
    for (int mat = 0; mat < 2; mat++) {
        const bf16* src = mat ? ql : qh;
        #pragma unroll
        for (int i = 0; i < 8; i++) {
            int id = i*128 + tid;
            int r = id >> 4, c = id & 15;
            cp16(sb + mat*16384 + (c>>3)*8192 + r*128 + (((uint32_t)(c&7)*16) ^ ((uint32_t)(r&7)*16)),
                 src + ((size_t)((b*SS + q0 + r)*HQ + hq))*128 + c*8);
        }
    }
    CP_COMMIT(); CP_WAIT(0);
    __syncthreads();

    float o0a[32], o1a[32];
    #pragma unroll
    for (int i = 0; i < 32; i++) { o0a[i] = 0.f; o1a[i] = 0.f; }
    float m0 = -INFINITY, m1 = -INFINITY, l0 = 0.f, l1 = 0.f;
    const float scale = 0.08838834764831845f;

    for (int kt = 0; kt <= qt; kt++) {
        int n0 = kt * 64;
        __syncthreads();
        #pragma unroll
        for (int mat = 0; mat < 2; mat++) {
            const bf16* base = mat ? kl : kh;
            #pragma unroll
            for (int i = 0; i < 8; i++) {
                int id = i*128 + tid;
                int r = id >> 4, c = id & 15;
                cp16(sb + KH_OFF + mat*16384 + (c>>3)*8192 + r*128 + (((uint32_t)(c&7)*16) ^ ((uint32_t)(r&7)*16)),
                     base + ((size_t)((b*SS + n0 + r)*HKV + gkv))*128 + c*8);
            }
        }
        #pragma unroll
        for (int i = 0; i < 16; i++) {
            int id = i*128 + tid;
            int r = id >> 5, c = id & 31;
            cp16(sb + VS_OFF + (uint32_t)r*528 + (uint32_t)c*16,
                 v + (size_t)(b*SS + n0 + r)*KVDIM + gkv*128 + c*4);
        }
        CP_COMMIT(); CP_WAIT(0);
        __syncthreads();

        // ---- S = Q K^T (3-term) ----
        float sacc[8][4];
        #pragma unroll
        for (int nb = 0; nb < 8; nb++)
            #pragma unroll
            for (int c = 0; c < 4; c++) sacc[nb][c] = 0.f;
        #pragma unroll
        for (int kb = 0; kb < 8; kb++) {
            uint32_t half = (uint32_t)(kb>>2)*8192;
            uint32_t o0 = (uint32_t)((kb&3)*32 + 4*tig);
            uint32_t r0a = (uint32_t)row0*128, r1a = r0a + 8*128;
            uint32_t qhf[4], qlf[4];
            qhf[0] = lds32(sb + half + r0a + (o0^swz));
            qhf[1] = lds32(sb + half + r1a + (o0^swz));
            qhf[2] = lds32(sb + half + r0a + ((o0+16)^swz));
            qhf[3] = lds32(sb + half + r1a + ((o0+16)^swz));
            qlf[0] = lds32(sb + 16384 + half + r0a + (o0^swz));
            qlf[1] = lds32(sb + 16384 + half + r1a + (o0^swz));
            qlf[2] = lds32(sb + 16384 + half + r0a + ((o0+16)^swz));
            qlf[3] = lds32(sb + 16384 + half + r1a + ((o0+16)^swz));
            #pragma unroll
            for (int nb = 0; nb < 8; nb++) {
                uint32_t rB = (uint32_t)(nb*8 + g)*128;
                uint32_t bhf[2], blf[2];
                bhf[0] = lds32(sb + KH_OFF + half + rB + (o0^swz));
                bhf[1] = lds32(sb + KH_OFF + half + rB + ((o0+16)^swz));
                blf[0] = lds32(sb + KH_OFF + 16384 + half + rB + (o0^swz));
                blf[1] = lds32(sb + KH_OFF + 16384 + half + rB + ((o0+16)^swz));
                mma16816(sacc[nb], qhf, bhf);
                mma16816(sacc[nb], qhf, blf);
                mma16816(sacc[nb], qlf, bhf);
            }
        }

        // ---- online softmax ----
        #pragma unroll
        for (int nb = 0; nb < 8; nb++)
            #pragma unroll
            for (int c = 0; c < 4; c++) sacc[nb][c] *= scale;
        if (kt == qt) {
            #pragma unroll
            for (int nb = 0; nb < 8; nb++) {
                int col0 = nb*8 + 2*tig;
                if (col0     > row0) sacc[nb][0] = -INFINITY;
                if (col0 + 1 > row0) sacc[nb][1] = -INFINITY;
                if (col0     > row1) sacc[nb][2] = -INFINITY;
                if (col0 + 1 > row1) sacc[nb][3] = -INFINITY;
            }
        }
        float mx0 = -INFINITY, mx1 = -INFINITY;
        #pragma unroll
        for (int nb = 0; nb < 8; nb++) {
            mx0 = fmaxf(mx0, fmaxf(sacc[nb][0], sacc[nb][1]));
            mx1 = fmaxf(mx1, fmaxf(sacc[nb][2], sacc[nb][3]));
        }
        mx0 = fmaxf(mx0, __shfl_xor_sync(0xffffffffu, mx0, 1));
        mx0 = fmaxf(mx0, __shfl_xor_sync(0xffffffffu, mx0, 2));
        mx1 = fmaxf(mx1, __shfl_xor_sync(0xffffffffu, mx1, 1));
        mx1 = fmaxf(mx1, __shfl_xor_sync(0xffffffffu, mx1, 2));
        float mn0 = fmaxf(m0, mx0), mn1 = fmaxf(m1, mx1);
        float al0 = __expf(m0 - mn0), al1 = __expf(m1 - mn1);
        float rs0 = 0.f, rs1 = 0.f;
        #pragma unroll
        for (int nb = 0; nb < 8; nb++) {
            sacc[nb][0] = __expf(sacc[nb][0] - mn0); rs0 += sacc[nb][0];
            sacc[nb][1] = __expf(sacc[nb][1] - mn0); rs0 += sacc[nb][1];
            sacc[nb][2] = __expf(sacc[nb][2] - mn1); rs1 += sacc[nb][2];
            sacc[nb][3] = __expf(sacc[nb][3] - mn1); rs1 += sacc[nb][3];
        }
        rs0 += __shfl_xor_sync(0xffffffffu, rs0, 1);
        rs0 += __shfl_xor_sync(0xffffffffu, rs0, 2);
        rs1 += __shfl_xor_sync(0xffffffffu, rs1, 1);
        rs1 += __shfl_xor_sync(0xffffffffu, rs1, 2);
        l0 = l0*al0 + rs0; l1 = l1*al1 + rs1;
        m0 = mn0; m1 = mn1;
        #pragma unroll
        for (int i = 0; i < 32; i++) { o0a[i] *= al0; o1a[i] *= al1; }

        // ---- P -> smem fp32 ----
        #pragma unroll
        for (int nb = 0; nb < 8; nb++) {
            uint32_t cb = (uint32_t)(nb*8 + 2*tig)*4;
            *(volatile float*)(sm + PS_OFF + (uint32_t)row0*272 + cb)     = sacc[nb][0];
            *(volatile float*)(sm + PS_OFF + (uint32_t)row0*272 + cb + 4) = sacc[nb][1];
            *(volatile float*)(sm + PS_OFF + (uint32_t)row1*272 + cb)     = sacc[nb][2];
            *(volatile float*)(sm + PS_OFF + (uint32_t)row1*272 + cb + 4) = sacc[nb][3];
        }
        __syncwarp();

        // ---- O += P V (fp32 scalar) ----
        #pragma unroll 4
        for (int key = 0; key < 64; key++) {
            float p0 = *(volatile const float*)(sm + PS_OFF + (uint32_t)row0*272 + (uint32_t)key*4);
            float p1 = *(volatile const float*)(sm + PS_OFF + (uint32_t)row1*272 + (uint32_t)key*4);
            #pragma unroll
            for (int j4 = 0; j4 < 8; j4++) {
                float4 vv = *(const float4*)(sm + VS_OFF + (uint32_t)key*528
                                             + (uint32_t)(j4*16 + tig*4)*4);
                o0a[j4*4+0] += p0*vv.x; o0a[j4*4+1] += p0*vv.y;
                o0a[j4*4+2] += p0*vv.z; o0a[j4*4+3] += p0*vv.w;
                o1a[j4*4+0] += p1*vv.x; o1a[j4*4+1] += p1*vv.y;
                o1a[j4*4+2] += p1*vv.z; o1a[j4*4+3] += p1*vv.w;
            }
        }
    }

    // ---- epilogue: normalize, emit bf16 hi/lo directly ----
    float inv0 = 1.f / l0, inv1 = 1.f / l1;
    size_t b0 = (size_t)(b*SS + q0 + row0)*QDIM + hq*128;
    size_t b1 = (size_t)(b*SS + q0 + row1)*QDIM + hq*128;
    #pragma unroll
    for (int j4 = 0; j4 < 8; j4++) {
        #pragma unroll
        for (int jj = 0; jj < 4; jj++) {
            int d = j4*16 + tig*4 + jj;
            float v0 = o0a[j4*4+jj] * inv0;
            float v1 = o1a[j4*4+jj] * inv1;
            bf16 h0 = __float2bfloat16(v0);
            oh[b0 + d] = h0;
            ol[b0 + d] = __float2bfloat16(v0 - __bfloat162float(h0));
            bf16 h1 = __float2bfloat16(v1);
            oh[b1 + d] = h1;
            ol[b1 + d] = __float2bfloat16(v1 - __bfloat162float(h1));
        }
    }
}

// ---------------------------------------------------------------------------
extern "C" void kernel_launch(void* const* d_in, const int* in_sizes, int n_in,
                              void* d_out, int out_size) {
    const float* x  = (const float*)d_in[0];
    const float* qp = (const float*)d_in[1];
    const float* kp = (const float*)d_in[2];
    const float* vp = (const float*)d_in[3];
    const float* qb = (const float*)d_in[4];
    const float* kb = (const float*)d_in[5];
    const float* vb = (const float*)d_in[6];
    const float* op = (const float*)d_in[7];
    const float* lw = (const float*)d_in[8];
    float* out = (float*)d_out;

    bf16 *hhi, *hlo, *wqh, *wql, *wkh, *wkl, *wvh, *wvl, *woh, *wol;
    bf16 *qhp, *qlp, *khp, *klp, *athi, *atlo;
    float *q, *k, *v;
    cudaGetSymbolAddress((void**)&hhi, g_h_hi);
    cudaGetSymbolAddress((void**)&hlo, g_h_lo);
    cudaGetSymbolAddress((void**)&wqh, g_wq_hi);
    cudaGetSymbolAddress((void**)&wql, g_wq_lo);
    cudaGetSymbolAddress((void**)&wkh, g_wk_hi);
    cudaGetSymbolAddress((void**)&wkl, g_wk_lo);
    cudaGetSymbolAddress((void**)&wvh, g_wv_hi);
    cudaGetSymbolAddress((void**)&wvl, g_wv_lo);
    cudaGetSymbolAddress((void**)&woh, g_wo_hi);
    cudaGetSymbolAddress((void**)&wol, g_wo_lo);
    cudaGetSymbolAddress((void**)&qhp, g_qh);
    cudaGetSymbolAddress((void**)&qlp, g_ql);
    cudaGetSymbolAddress((void**)&khp, g_kh);
    cudaGetSymbolAddress((void**)&klp, g_kl);
    cudaGetSymbolAddress((void**)&athi, g_att_hi);
    cudaGetSymbolAddress((void**)&atlo, g_att_lo);
    cudaGetSymbolAddress((void**)&q, g_q);
    cudaGetSymbolAddress((void**)&k, g_k);
    cudaGetSymbolAddress((void**)&v, g_v);

    cudaFuncSetAttribute(gemm_mma, cudaFuncAttributeMaxDynamicSharedMemorySize, 131072);
    cudaFuncSetAttribute(attn_smma, cudaFuncAttributeMaxDynamicSharedMemorySize, ATTN_SMEM);

    // 0. split weights (validated)
    split_kernel<<<(QDIM*HID/4 + 255)/256, 256>>>(qp, wqh, wql, QDIM*HID/4);
    split_kernel<<<(KVDIM*HID/4 + 255)/256, 256>>>(kp, wkh, wkl, KVDIM*HID/4);
    split_kernel<<<(KVDIM*HID/4 + 255)/256, 256>>>(vp, wvh, wvl, KVDIM*HID/4);
    split_kernel<<<(HID*QDIM/4 + 255)/256, 256>>>(op, woh, wol, HID*QDIM/4);

    // 1. RMSNorm -> hi/lo (validated)
    rmsnorm_kernel<<<MM, 256>>>(x, lw, hhi, hlo);

    // 2. projections (512-thread gemm, fp32 out)
    {
        dim3 gq(QDIM/128, MM/128);
        gemm_mma<<<gq, 512, 131072>>>(hhi, hlo, wqh, wql, qb, q, QDIM);
        dim3 gkv(KVDIM/128, MM/128);
        gemm_mma<<<gkv, 512, 131072>>>(hhi, hlo, wkh, wkl, kb, k, KVDIM);
        gemm_mma<<<gkv, 512, 131072>>>(hhi, hlo, wvh, wvl, vb, v, KVDIM);
    }

    // 3. RoPE -> hi/lo
    {
        int totq = BB * SS * HQ * 64;
        rope_split_kernel<<<(totq + 255)/256, 256>>>(q, qhp, qlp, HQ, totq);
        int totk = BB * SS * HKV * 64;
        rope_split_kernel<<<(totk + 255)/256, 256>>>(k, khp, klp, HKV, totk);
    }

    // 4. attention: HMMA S + fp32 PV -> bf16 hi/lo directly
    {
        dim3 ga(SS/64, HQ, BB);
        attn_smma<<<ga, 128, ATTN_SMEM>>>(qhp, qlp, khp, klp, v, athi, atlo);
    }

    // 5. O projection (512-thread gemm) -> fp32 out
    {
        dim3 go(HID/128, MM/128);
        gemm_mma<<<go, 512, 131072>>>(athi, atlo, woh, wol, nullptr, out, HID);
    }
}

// round 10
// speedup vs baseline: 1.0534x; 1.0534x over previous
#include <cuda_runtime.h>
#include <cuda_bf16.h>
#include <cstdint>
#include <math.h>

typedef __nv_bfloat16 bf16;

#define BB   2
#define SS   2048
#define HID  2048
#define HQ   16
#define HKV  4
#define MM   (BB*SS)          // 4096
#define QDIM 2048
#define KVDIM 512

// ---------------- scratch ----------------
__device__ __align__(16) bf16 g_h_hi[MM*HID];
__device__ __align__(16) bf16 g_h_lo[MM*HID];
__device__ __align__(16) bf16 g_wq_hi[QDIM*HID];
__device__ __align__(16) bf16 g_wq_lo[QDIM*HID];
__device__ __align__(16) bf16 g_wk_hi[KVDIM*HID];
__device__ __align__(16) bf16 g_wk_lo[KVDIM*HID];
__device__ __align__(16) bf16 g_wv_hi[KVDIM*HID];
__device__ __align__(16) bf16 g_wv_lo[KVDIM*HID];
__device__ __align__(16) bf16 g_wo_hi[HID*QDIM];
__device__ __align__(16) bf16 g_wo_lo[HID*QDIM];
__device__ __align__(16) float g_q[MM*QDIM];
__device__ __align__(16) float g_k[MM*KVDIM];
__device__ __align__(16) float g_v[MM*KVDIM];
__device__ __align__(16) bf16 g_qh[MM*QDIM];
__device__ __align__(16) bf16 g_ql[MM*QDIM];
__device__ __align__(16) bf16 g_kh[MM*KVDIM];
__device__ __align__(16) bf16 g_kl[MM*KVDIM];
__device__ __align__(16) bf16 g_att_hi[MM*QDIM];
__device__ __align__(16) bf16 g_att_lo[MM*QDIM];

// ---------------- helpers ----------------
__device__ __forceinline__ uint32_t smem_u32(const void* p) {
    uint32_t a;
    asm("{ .reg .u64 t; cvta.to.shared.u64 t, %1; cvt.u32.u64 %0, t; }" : "=r"(a) : "l"(p));
    return a;
}
__device__ __forceinline__ void cp16(uint32_t dst, const void* src) {
    asm volatile("cp.async.cg.shared.global [%0], [%1], 16;" :: "r"(dst), "l"(src));
}
#define CP_COMMIT() asm volatile("cp.async.commit_group;" ::: "memory")
#define CP_WAIT(n)  asm volatile("cp.async.wait_group %0;" :: "n"(n) : "memory")

// volatile + memory clobber (attention path; pinned in program order)
__device__ __forceinline__ uint32_t lds32(uint32_t a) {
    uint32_t v;
    asm volatile("ld.shared.b32 %0, [%1];" : "=r"(v) : "r"(a) : "memory");
    return v;
}
// ldmatrix x4 non-trans (gemm path; volatile, no clobber -> schedulable)
__device__ __forceinline__ void ldsm_x4(uint32_t& r0, uint32_t& r1, uint32_t& r2,
                                        uint32_t& r3, uint32_t a) {
    asm volatile("ldmatrix.sync.aligned.m8n8.x4.shared.b16 {%0,%1,%2,%3}, [%4];"
                 : "=r"(r0), "=r"(r1), "=r"(r2), "=r"(r3) : "r"(a));
}
__device__ __forceinline__ void mma16816(float* d, const uint32_t* a, const uint32_t* b) {
    asm volatile("mma.sync.aligned.m16n8k16.row.col.f32.bf16.bf16.f32 "
        "{%0,%1,%2,%3}, {%4,%5,%6,%7}, {%8,%9}, {%0,%1,%2,%3};"
        : "+f"(d[0]), "+f"(d[1]), "+f"(d[2]), "+f"(d[3])
        : "r"(a[0]), "r"(a[1]), "r"(a[2]), "r"(a[3]), "r"(b[0]), "r"(b[1]));
}

// ---------------------------------------------------------------------------
// RMSNorm -> bf16 hi/lo (validated)
// ---------------------------------------------------------------------------
__global__ void rmsnorm_kernel(const float* __restrict__ x,
                               const float* __restrict__ w,
                               bf16* __restrict__ ohi, bf16* __restrict__ olo) {
    int row = blockIdx.x;
    int tid = threadIdx.x;
    const float4* xr = (const float4*)(x + (size_t)row * HID);
    float4 a = xr[tid];
    float4 b = xr[tid + 256];
    float ss = a.x*a.x + a.y*a.y + a.z*a.z + a.w*a.w
             + b.x*b.x + b.y*b.y + b.z*b.z + b.w*b.w;
    #pragma unroll
    for (int off = 16; off > 0; off >>= 1)
        ss += __shfl_xor_sync(0xffffffffu, ss, off);
    __shared__ float sred[8];
    __shared__ float sinv;
    if ((tid & 31) == 0) sred[tid >> 5] = ss;
    __syncthreads();
    if (tid == 0) {
        float t = 0.f;
        #pragma unroll
        for (int i = 0; i < 8; i++) t += sred[i];
        sinv = rsqrtf(t / (float)HID + 1e-6f);
    }
    __syncthreads();
    float inv = sinv;
    const float4* wr = (const float4*)w;
    float4 wa = wr[tid], wb = wr[tid + 256];
    float va[8] = { a.x*inv*wa.x, a.y*inv*wa.y, a.z*inv*wa.z, a.w*inv*wa.w,
                    b.x*inv*wb.x, b.y*inv*wb.y, b.z*inv*wb.z, b.w*inv*wb.w };
    size_t base0 = (size_t)row * HID + tid*4;
    size_t base1 = (size_t)row * HID + (tid+256)*4;
    #pragma unroll
    for (int i = 0; i < 4; i++) {
        bf16 h0 = __float2bfloat16(va[i]);
        ohi[base0+i] = h0;
        olo[base0+i] = __float2bfloat16(va[i] - __bfloat162float(h0));
        bf16 h1 = __float2bfloat16(va[4+i]);
        ohi[base1+i] = h1;
        olo[base1+i] = __float2bfloat16(va[4+i] - __bfloat162float(h1));
    }
}

// ---------------------------------------------------------------------------
// split fp32 -> bf16 hi/lo (validated)
// ---------------------------------------------------------------------------
__global__ void split_kernel(const float* __restrict__ in, bf16* __restrict__ hi,
                             bf16* __restrict__ lo, int n4) {
    int i = blockIdx.x * 256 + threadIdx.x;
    if (i >= n4) return;
    float4 v = ((const float4*)in)[i];
    bf16 h0 = __float2bfloat16(v.x), h1 = __float2bfloat16(v.y);
    bf16 h2 = __float2bfloat16(v.z), h3 = __float2bfloat16(v.w);
    __nv_bfloat162 hh0; hh0.x = h0; hh0.y = h1;
    __nv_bfloat162 hh1; hh1.x = h2; hh1.y = h3;
    __nv_bfloat162 ll0, ll1;
    ll0.x = __float2bfloat16(v.x - __bfloat162float(h0));
    ll0.y = __float2bfloat16(v.y - __bfloat162float(h1));
    ll1.x = __float2bfloat16(v.z - __bfloat162float(h2));
    ll1.y = __float2bfloat16(v.w - __bfloat162float(h3));
    ((__nv_bfloat162*)hi)[i*2+0] = hh0;
    ((__nv_bfloat162*)hi)[i*2+1] = hh1;
    ((__nv_bfloat162*)lo)[i*2+0] = ll0;
    ((__nv_bfloat162*)lo)[i*2+1] = ll1;
}

// ---------------------------------------------------------------------------
// HMMA GEMM (NT): 256 threads (R8 shape), ldmatrix.x4 fragment loads.
// Warp grid 2(m) x 4(n), warp tile 64x32. Tile 128x128, K-chunk 64,
// cp.async double-buffered. smem 131072 B.
// Fragment reg<->matrix mapping: ldmatrix.x4 matrix i -> reg i, with
// matrices = (rows 0-7 / 8-15) x (k-lo / k-hi) == the validated lds32 layout.
// ---------------------------------------------------------------------------
__global__ __launch_bounds__(256, 1)
void gemm_mma(const bf16* __restrict__ Ah, const bf16* __restrict__ Al,
              const bf16* __restrict__ Bh, const bf16* __restrict__ Bl,
              const float* __restrict__ bias, float* __restrict__ Cf, int N) {
    extern __shared__ __align__(128) char sm[];
    uint32_t sb = smem_u32(sm);
    int tid = threadIdx.x;
    int w = tid >> 5, lane = tid & 31, g = lane >> 2, tig = lane & 3;
    int wm = w & 1, wn = w >> 1;
    int brow = blockIdx.y * 128, bcol = blockIdx.x * 128;

    float acc[4][4][4];
    #pragma unroll
    for (int a = 0; a < 4; a++)
        #pragma unroll
        for (int b = 0; b < 4; b++)
            #pragma unroll
            for (int c = 0; c < 4; c++) acc[a][b][c] = 0.f;

    auto load_stage = [&](int s, int ck) {
        #pragma unroll
        for (int mat = 0; mat < 4; mat++) {
            const bf16* base = (mat == 0) ? Ah : (mat == 1) ? Al : (mat == 2) ? Bh : Bl;
            int ro = (mat < 2) ? brow : bcol;
            #pragma unroll
            for (int i = 0; i < 4; i++) {
                int id = i*256 + tid;
                int r = id >> 3, c = id & 7;
                cp16(sb + s*65536 + mat*16384 + r*128 + (((uint32_t)c*16) ^ ((uint32_t)(r&7)*16)),
                     base + (size_t)(ro + r)*2048 + ck*64 + c*8);
            }
        }
    };

    // ldmatrix lane-address components (constant per thread)
    uint32_t lswz = (uint32_t)(lane & 7) * 16;            // swizzle XOR for this lane's rows
    uint32_t a_row = (uint32_t)(lane & 15);               // A: row offset within 16-row tile
    uint32_t a_kb  = (lane & 16) ? 16u : 0u;              // A: k-half byte offset
    uint32_t b_row = (uint32_t)((lane & 16) ? 8 : 0) + (lane & 7);  // B: row offset within pair
    uint32_t b_kb  = (lane & 8) ? 16u : 0u;               // B: k-half byte offset

    load_stage(0, 0);
    CP_COMMIT();

    for (int ck = 0; ck < 32; ck++) {
        if (ck + 1 < 32) { load_stage((ck+1)&1, ck+1); CP_COMMIT(); CP_WAIT(1); }
        else             { CP_WAIT(0); }
        __syncthreads();
        uint32_t tb = sb + (ck&1)*65536;
        #pragma unroll
        for (int ks = 0; ks < 4; ks++) {
            uint32_t ksb = (uint32_t)(32*ks);
            uint32_t ah[4][4], al[4][4];
            #pragma unroll
            for (int mb = 0; mb < 4; mb++) {
                uint32_t r = (uint32_t)(wm*64 + mb*16) + a_row;
                uint32_t addr = tb + r*128 + ((ksb + a_kb) ^ lswz);
                ldsm_x4(ah[mb][0], ah[mb][1], ah[mb][2], ah[mb][3], addr);
                ldsm_x4(al[mb][0], al[mb][1], al[mb][2], al[mb][3], addr + 16384);
            }
            uint32_t bh[4][2], bl[4][2];
            #pragma unroll
            for (int pr = 0; pr < 2; pr++) {
                uint32_t r = (uint32_t)(wn*32 + pr*16) + b_row;
                uint32_t addr = tb + 2*16384 + r*128 + ((ksb + b_kb) ^ lswz);
                ldsm_x4(bh[pr*2][0], bh[pr*2][1], bh[pr*2+1][0], bh[pr*2+1][1], addr);
                ldsm_x4(bl[pr*2][0], bl[pr*2][1], bl[pr*2+1][0], bl[pr*2+1][1], addr + 16384);
            }
            #pragma unroll
            for (int mb = 0; mb < 4; mb++)
                #pragma unroll
                for (int nb = 0; nb < 4; nb++) {
                    mma16816(acc[mb][nb], ah[mb], bh[nb]);
                    mma16816(acc[mb][nb], ah[mb], bl[nb]);
                    mma16816(acc[mb][nb], al[mb], bh[nb]);
                }
        }
        __syncthreads();
    }

    #pragma unroll
    for (int mb = 0; mb < 4; mb++) {
        #pragma unroll
        for (int half = 0; half < 2; half++) {
            int row = brow + wm*64 + mb*16 + g + 8*half;
            #pragma unroll
            for (int nb = 0; nb < 4; nb++) {
                int col = bcol + wn*32 + nb*8 + 2*tig;
                float v0 = acc[mb][nb][2*half];
                float v1 = acc[mb][nb][2*half+1];
                if (bias) { v0 += bias[col]; v1 += bias[col+1]; }
                *(float2*)(Cf + (size_t)row * N + col) = make_float2(v0, v1);
            }
        }
    }
}

// ---------------------------------------------------------------------------
// RoPE: fp32 in -> bf16 hi/lo out (validated)
// ---------------------------------------------------------------------------
__global__ void rope_split_kernel(const float* __restrict__ t,
                                  bf16* __restrict__ oh, bf16* __restrict__ ol,
                                  int nHeads, int total) {
    int idx = blockIdx.x * blockDim.x + threadIdx.x;
    if (idx >= total) return;
    int j = idx & 63;
    int h = (idx >> 6) % nHeads;
    int s = (idx / (64 * nHeads)) % SS;
    int b = idx / (64 * nHeads * SS);
    float inv_freq = expf(-((float)(2*j) / 128.f) * logf(10000.f));
    float ang = (float)s * inv_freq;
    float c, sn;
    sincosf(ang, &sn, &c);
    size_t base = ((size_t)(b*SS + s) * nHeads + h) * 128;
    float a0 = t[base + j];
    float a1 = t[base + j + 64];
    float r0 = a0 * c - a1 * sn;
    float r1 = a1 * c + a0 * sn;
    bf16 h0 = __float2bfloat16(r0);
    oh[base + j] = h0;
    ol[base + j] = __float2bfloat16(r0 - __bfloat162float(h0));
    bf16 h1 = __float2bfloat16(r1);
    oh[base + j + 64] = h1;
    ol[base + j + 64] = __float2bfloat16(r1 - __bfloat162float(h1));
}

// ---------------------------------------------------------------------------
// Attention: HMMA S = QK^T (3-term hi/lo) + register softmax + fp32 PV.
// (validated round 8/9, unchanged)
// ---------------------------------------------------------------------------
#define KH_OFF 32768
#define VS_OFF 65536
#define PS_OFF 99328
#define ATTN_SMEM 116736

__global__ __launch_bounds__(128)
void attn_smma(const bf16* __restrict__ qh, const bf16* __restrict__ ql,
               const bf16* __restrict__ kh, const bf16* __restrict__ kl,
               const float* __restrict__ v,
               bf16* __restrict__ oh, bf16* __restrict__ ol) {
    extern __shared__ __align__(128) char sm[];
    uint32_t sb = smem_u32(sm);
    int tid = threadIdx.x, w = tid >> 5, lane = tid & 31, g = lane >> 2, tig = lane & 3;
    int qt = gridDim.x - 1 - blockIdx.x;
    int hq = blockIdx.y, b = blockIdx.z, gkv = hq >> 2;
    int q0 = qt * 64;
    uint32_t swz = (uint32_t)g*16;
    int row0 = w*16 + g, row1 = row0 + 8;

    #pragma unroll
    for (int mat = 0; mat < 2; mat++) {
        const bf16* src = mat ? ql : qh;
        #pragma unroll
        for (int i = 0; i < 8; i++) {
            int id = i*128 + tid;
            int r = id >> 4, c = id & 15;
            cp16(sb + mat*16384 + (c>>3)*8192 + r*128 + (((uint32_t)(c&7)*16) ^ ((uint32_t)(r&7)*16)),
                 src + ((size_t)((b*SS + q0 + r)*HQ + hq))*128 + c*8);
        }
    }
    CP_COMMIT(); CP_WAIT(0);
    __syncthreads();

    float o0a[32], o1a[32];
    #pragma unroll
    for (int i = 0; i < 32; i++) { o0a[i] = 0.f; o1a[i] = 0.f; }
    float m0 = -INFINITY, m1 = -INFINITY, l0 = 0.f, l1 = 0.f;
    const float scale = 0.08838834764831845f;

    for (int kt = 0; kt <= qt; kt++) {
        int n0 = kt * 64;
        __syncthreads();
        #pragma unroll
        for (int mat = 0; mat < 2; mat++) {
            const bf16* base = mat ? kl : kh;
            #pragma unroll
            for (int i = 0; i < 8; i++) {
                int id = i*128 + tid;
                int r = id >> 4, c = id & 15;
                cp16(sb + KH_OFF + mat*16384 + (c>>3)*8192 + r*128 + (((uint32_t)(c&7)*16) ^ ((uint32_t)(r&7)*16)),
                     base + ((size_t)((b*SS + n0 + r)*HKV + gkv))*128 + c*8);
            }
        }
        #pragma unroll
        for (int i = 0; i < 16; i++) {
            int id = i*128 + tid;
            int r = id >> 5, c = id & 31;
            cp16(sb + VS_OFF + (uint32_t)r*528 + (uint32_t)c*16,
                 v + (size_t)(b*SS + n0 + r)*KVDIM + gkv*128 + c*4);
        }
        CP_COMMIT(); CP_WAIT(0);
        __syncthreads();

        float sacc[8][4];
        #pragma unroll
        for (int nb = 0; nb < 8; nb++)
            #pragma unroll
            for (int c = 0; c < 4; c++) sacc[nb][c] = 0.f;
        #pragma unroll
        for (int kb = 0; kb < 8; kb++) {
            uint32_t half = (uint32_t)(kb>>2)*8192;
            uint32_t o0 = (uint32_t)((kb&3)*32 + 4*tig);
            uint32_t r0a = (uint32_t)row0*128, r1a = r0a + 8*128;
            uint32_t qhf[4], qlf[4];
            qhf[0] = lds32(sb + half + r0a + (o0^swz));
            qhf[1] = lds32(sb + half + r1a + (o0^swz));
            qhf[2] = lds32(sb + half + r0a + ((o0+16)^swz));
            qhf[3] = lds32(sb + half + r1a + ((o0+16)^swz));
            qlf[0] = lds32(sb + 16384 + half + r0a + (o0^swz));
            qlf[1] = lds32(sb + 16384 + half + r1a + (o0^swz));
            qlf[2] = lds32(sb + 16384 + half + r0a + ((o0+16)^swz));
            qlf[3] = lds32(sb + 16384 + half + r1a + ((o0+16)^swz));
            #pragma unroll
            for (int nb = 0; nb < 8; nb++) {
                uint32_t rB = (uint32_t)(nb*8 + g)*128;
                uint32_t bhf[2], blf[2];
                bhf[0] = lds32(sb + KH_OFF + half + rB + (o0^swz));
                bhf[1] = lds32(sb + KH_OFF + half + rB + ((o0+16)^swz));
                blf[0] = lds32(sb + KH_OFF + 16384 + half + rB + (o0^swz));
                blf[1] = lds32(sb + KH_OFF + 16384 + half + rB + ((o0+16)^swz));
                mma16816(sacc[nb], qhf, bhf);
                mma16816(sacc[nb], qhf, blf);
                mma16816(sacc[nb], qlf, bhf);
            }
        }

        #pragma unroll
        for (int nb = 0; nb < 8; nb++)
            #pragma unroll
            for (int c = 0; c < 4; c++) sacc[nb][c] *= scale;
        if (kt == qt) {
            #pragma unroll
            for (int nb = 0; nb < 8; nb++) {
                int col0 = nb*8 + 2*tig;
                if (col0     > row0) sacc[nb][0] = -INFINITY;
                if (col0 + 1 > row0) sacc[nb][1] = -INFINITY;
                if (col0     > row1) sacc[nb][2] = -INFINITY;
                if (col0 + 1 > row1) sacc[nb][3] = -INFINITY;
            }
        }
        float mx0 = -INFINITY, mx1 = -INFINITY;
        #pragma unroll
        for (int nb = 0; nb < 8; nb++) {
            mx0 = fmaxf(mx0, fmaxf(sacc[nb][0], sacc[nb][1]));
            mx1 = fmaxf(mx1, fmaxf(sacc[nb][2], sacc[nb][3]));
        }
        mx0 = fmaxf(mx0, __shfl_xor_sync(0xffffffffu, mx0, 1));
        mx0 = fmaxf(mx0, __shfl_xor_sync(0xffffffffu, mx0, 2));
        mx1 = fmaxf(mx1, __shfl_xor_sync(0xffffffffu, mx1, 1));
        mx1 = fmaxf(mx1, __shfl_xor_sync(0xffffffffu, mx1, 2));
        float mn0 = fmaxf(m0, mx0), mn1 = fmaxf(m1, mx1);
        float al0 = __expf(m0 - mn0), al1 = __expf(m1 - mn1);
        float rs0 = 0.f, rs1 = 0.f;
        #pragma unroll
        for (int nb = 0; nb < 8; nb++) {
            sacc[nb][0] = __expf(sacc[nb][0] - mn0); rs0 += sacc[nb][0];
            sacc[nb][1] = __expf(sacc[nb][1] - mn0); rs0 += sacc[nb][1];
            sacc[nb][2] = __expf(sacc[nb][2] - mn1); rs1 += sacc[nb][2];
            sacc[nb][3] = __expf(sacc[nb][3] - mn1); rs1 += sacc[nb][3];
        }
        rs0 += __shfl_xor_sync(0xffffffffu, rs0, 1);
        rs0 += __shfl_xor_sync(0xffffffffu, rs0, 2);
        rs1 += __shfl_xor_sync(0xffffffffu, rs1, 1);
        rs1 += __shfl_xor_sync(0xffffffffu, rs1, 2);
        l0 = l0*al0 + rs0; l1 = l1*al1 + rs1;
        m0 = mn0; m1 = mn1;
        #pragma unroll
        for (int i = 0; i < 32; i++) { o0a[i] *= al0; o1a[i] *= al1; }

        #pragma unroll
        for (int nb = 0; nb < 8; nb++) {
            uint32_t cb = (uint32_t)(nb*8 + 2*tig)*4;
            *(volatile float*)(sm + PS_OFF + (uint32_t)row0*272 + cb)     = sacc[nb][0];
            *(volatile float*)(sm + PS_OFF + (uint32_t)row0*272 + cb + 4) = sacc[nb][1];
            *(volatile float*)(sm + PS_OFF + (uint32_t)row1*272 + cb)     = sacc[nb][2];
            *(volatile float*)(sm + PS_OFF + (uint32_t)row1*272 + cb + 4) = sacc[nb][3];
        }
        __syncwarp();

        #pragma unroll 4
        for (int key = 0; key < 64; key++) {
            float p0 = *(volatile const float*)(sm + PS_OFF + (uint32_t)row0*272 + (uint32_t)key*4);
            float p1 = *(volatile const float*)(sm + PS_OFF + (uint32_t)row1*272 + (uint32_t)key*4);
            #pragma unroll
            for (int j4 = 0; j4 < 8; j4++) {
                float4 vv = *(const float4*)(sm + VS_OFF + (uint32_t)key*528
                                             + (uint32_t)(j4*16 + tig*4)*4);
                o0a[j4*4+0] += p0*vv.x; o0a[j4*4+1] += p0*vv.y;
                o0a[j4*4+2] += p0*vv.z; o0a[j4*4+3] += p0*vv.w;
                o1a[j4*4+0] += p1*vv.x; o1a[j4*4+1] += p1*vv.y;
                o1a[j4*4+2] += p1*vv.z; o1a[j4*4+3] += p1*vv.w;
            }
        }
    }

    float inv0 = 1.f / l0, inv1 = 1.f / l1;
    size_t b0 = (size_t)(b*SS + q0 + row0)*QDIM + hq*128;
    size_t b1 = (size_t)(b*SS + q0 + row1)*QDIM + hq*128;
    #pragma unroll
    for (int j4 = 0; j4 < 8; j4++) {
        #pragma unroll
        for (int jj = 0; jj < 4; jj++) {
            int d = j4*16 + tig*4 + jj;
            float v0 = o0a[j4*4+jj] * inv0;
            float v1 = o1a[j4*4+jj] * inv1;
            bf16 h0 = __float2bfloat16(v0);
            oh[b0 + d] = h0;
            ol[b0 + d] = __float2bfloat16(v0 - __bfloat162float(h0));
            bf16 h1 = __float2bfloat16(v1);
            oh[b1 + d] = h1;
            ol[b1 + d] = __float2bfloat16(v1 - __bfloat162float(h1));
        }
    }
}

// ---------------------------------------------------------------------------
extern "C" void kernel_launch(void* const* d_in, const int* in_sizes, int n_in,
                              void* d_out, int out_size) {
    const float* x  = (const float*)d_in[0];
    const float* qp = (const float*)d_in[1];
    const float* kp = (const float*)d_in[2];
    const float* vp = (const float*)d_in[3];
    const float* qb = (const float*)d_in[4];
    const float* kb = (const float*)d_in[5];
    const float* vb = (const float*)d_in[6];
    const float* op = (const float*)d_in[7];
    const float* lw = (const float*)d_in[8];
    float* out = (float*)d_out;

    bf16 *hhi, *hlo, *wqh, *wql, *wkh, *wkl, *wvh, *wvl, *woh, *wol;
    bf16 *qhp, *qlp, *khp, *klp, *athi, *atlo;
    float *q, *k, *v;
    cudaGetSymbolAddress((void**)&hhi, g_h_hi);
    cudaGetSymbolAddress((void**)&hlo, g_h_lo);
    cudaGetSymbolAddress((void**)&wqh, g_wq_hi);
    cudaGetSymbolAddress((void**)&wql, g_wq_lo);
    cudaGetSymbolAddress((void**)&wkh, g_wk_hi);
    cudaGetSymbolAddress((void**)&wkl, g_wk_lo);
    cudaGetSymbolAddress((void**)&wvh, g_wv_hi);
    cudaGetSymbolAddress((void**)&wvl, g_wv_lo);
    cudaGetSymbolAddress((void**)&woh, g_wo_hi);
    cudaGetSymbolAddress((void**)&wol, g_wo_lo);
    cudaGetSymbolAddress((void**)&qhp, g_qh);
    cudaGetSymbolAddress((void**)&qlp, g_ql);
    cudaGetSymbolAddress((void**)&khp, g_kh);
    cudaGetSymbolAddress((void**)&klp, g_kl);
    cudaGetSymbolAddress((void**)&athi, g_att_hi);
    cudaGetSymbolAddress((void**)&atlo, g_att_lo);
    cudaGetSymbolAddress((void**)&q, g_q);
    cudaGetSymbolAddress((void**)&k, g_k);
    cudaGetSymbolAddress((void**)&v, g_v);

    cudaFuncSetAttribute(gemm_mma, cudaFuncAttributeMaxDynamicSharedMemorySize, 131072);
    cudaFuncSetAttribute(attn_smma, cudaFuncAttributeMaxDynamicSharedMemorySize, ATTN_SMEM);

    // 0. split weights (validated)
    split_kernel<<<(QDIM*HID/4 + 255)/256, 256>>>(qp, wqh, wql, QDIM*HID/4);
    split_kernel<<<(KVDIM*HID/4 + 255)/256, 256>>>(kp, wkh, wkl, KVDIM*HID/4);
    split_kernel<<<(KVDIM*HID/4 + 255)/256, 256>>>(vp, wvh, wvl, KVDIM*HID/4);
    split_kernel<<<(HID*QDIM/4 + 255)/256, 256>>>(op, woh, wol, HID*QDIM/4);

    // 1. RMSNorm -> hi/lo (validated)
    rmsnorm_kernel<<<MM, 256>>>(x, lw, hhi, hlo);

    // 2. projections (256-thread gemm + ldmatrix, fp32 out)
    {
        dim3 gq(QDIM/128, MM/128);
        gemm_mma<<<gq, 256, 131072>>>(hhi, hlo, wqh, wql, qb, q, QDIM);
        dim3 gkv(KVDIM/128, MM/128);
        gemm_mma<<<gkv, 256, 131072>>>(hhi, hlo, wkh, wkl, kb, k, KVDIM);
        gemm_mma<<<gkv, 256, 131072>>>(hhi, hlo, wvh, wvl, vb, v, KVDIM);
    }

    // 3. RoPE -> hi/lo
    {
        int totq = BB * SS * HQ * 64;
        rope_split_kernel<<<(totq + 255)/256, 256>>>(q, qhp, qlp, HQ, totq);
        int totk = BB * SS * HKV * 64;
        rope_split_kernel<<<(totk + 255)/256, 256>>>(k, khp, klp, HKV, totk);
    }

    // 4. attention: HMMA S + fp32 PV -> bf16 hi/lo directly (validated)
    {
        dim3 ga(SS/64, HQ, BB);
        attn_smma<<<ga, 128, ATTN_SMEM>>>(qhp, qlp, khp, klp, v, athi, atlo);
    }

    // 5. O projection -> fp32 out
    {
        dim3 go(HID/128, MM/128);
        gemm_mma<<<go, 256, 131072>>>(athi, atlo, woh, wol, nullptr, out, HID);
    }
}

// round 12
// speedup vs baseline: 1.6761x; 1.5911x over previous
#include <cuda_runtime.h>
#include <cuda_bf16.h>
#include <cstdint>
#include <math.h>

typedef __nv_bfloat16 bf16;

#define BB   2
#define SS   2048
#define HID  2048
#define HQ   16
#define HKV  4
#define MM   (BB*SS)          // 4096
#define QDIM 2048
#define KVDIM 512

// ---------------- scratch ----------------
__device__ __align__(16) bf16 g_h_hi[MM*HID];
__device__ __align__(16) bf16 g_h_lo[MM*HID];
__device__ __align__(16) bf16 g_wq_hi[QDIM*HID];
__device__ __align__(16) bf16 g_wq_lo[QDIM*HID];
__device__ __align__(16) bf16 g_wk_hi[KVDIM*HID];
__device__ __align__(16) bf16 g_wk_lo[KVDIM*HID];
__device__ __align__(16) bf16 g_wv_hi[KVDIM*HID];
__device__ __align__(16) bf16 g_wv_lo[KVDIM*HID];
__device__ __align__(16) bf16 g_wo_hi[HID*QDIM];
__device__ __align__(16) bf16 g_wo_lo[HID*QDIM];
__device__ __align__(16) float g_q[MM*QDIM];
__device__ __align__(16) float g_k[MM*KVDIM];
__device__ __align__(16) bf16 g_qh[MM*QDIM];
__device__ __align__(16) bf16 g_ql[MM*QDIM];
__device__ __align__(16) bf16 g_kh[MM*KVDIM];
__device__ __align__(16) bf16 g_kl[MM*KVDIM];
__device__ __align__(16) bf16 g_vth[MM*KVDIM];   // V^T: [b][hkv][d][s]
__device__ __align__(16) bf16 g_vtl[MM*KVDIM];
__device__ __align__(16) bf16 g_att_hi[MM*QDIM];
__device__ __align__(16) bf16 g_att_lo[MM*QDIM];

// ---------------- helpers ----------------
__device__ __forceinline__ uint32_t smem_u32(const void* p) {
    uint32_t a;
    asm("{ .reg .u64 t; cvta.to.shared.u64 t, %1; cvt.u32.u64 %0, t; }" : "=r"(a) : "l"(p));
    return a;
}
__device__ __forceinline__ void cp16(uint32_t dst, const void* src) {
    asm volatile("cp.async.cg.shared.global [%0], [%1], 16;" :: "r"(dst), "l"(src));
}
#define CP_COMMIT() asm volatile("cp.async.commit_group;" ::: "memory")
#define CP_WAIT(n)  asm volatile("cp.async.wait_group %0;" :: "n"(n) : "memory")

__device__ __forceinline__ uint32_t lds32(uint32_t a) {
    uint32_t v;
    asm volatile("ld.shared.b32 %0, [%1];" : "=r"(v) : "r"(a) : "memory");
    return v;
}
__device__ __forceinline__ void ldsm_x4(uint32_t& r0, uint32_t& r1, uint32_t& r2,
                                        uint32_t& r3, uint32_t a) {
    asm volatile("ldmatrix.sync.aligned.m8n8.x4.shared.b16 {%0,%1,%2,%3}, [%4];"
                 : "=r"(r0), "=r"(r1), "=r"(r2), "=r"(r3) : "r"(a));
}
__device__ __forceinline__ void mma16816(float* d, const uint32_t* a, const uint32_t* b) {
    asm volatile("mma.sync.aligned.m16n8k16.row.col.f32.bf16.bf16.f32 "
        "{%0,%1,%2,%3}, {%4,%5,%6,%7}, {%8,%9}, {%0,%1,%2,%3};"
        : "+f"(d[0]), "+f"(d[1]), "+f"(d[2]), "+f"(d[3])
        : "r"(a[0]), "r"(a[1]), "r"(a[2]), "r"(a[3]), "r"(b[0]), "r"(b[1]));
}
__device__ __forceinline__ uint32_t packbf(float x, float y) {
    __nv_bfloat162 t;
    t.x = __float2bfloat16(x); t.y = __float2bfloat16(y);
    uint32_t u; memcpy(&u, &t, 4); return u;
}

// ---------------------------------------------------------------------------
// RMSNorm -> bf16 hi/lo (validated)
// ---------------------------------------------------------------------------
__global__ void rmsnorm_kernel(const float* __restrict__ x,
                               const float* __restrict__ w,
                               bf16* __restrict__ ohi, bf16* __restrict__ olo) {
    int row = blockIdx.x;
    int tid = threadIdx.x;
    const float4* xr = (const float4*)(x + (size_t)row * HID);
    float4 a = xr[tid];
    float4 b = xr[tid + 256];
    float ss = a.x*a.x + a.y*a.y + a.z*a.z + a.w*a.w
             + b.x*b.x + b.y*b.y + b.z*b.z + b.w*b.w;
    #pragma unroll
    for (int off = 16; off > 0; off >>= 1)
        ss += __shfl_xor_sync(0xffffffffu, ss, off);
    __shared__ float sred[8];
    __shared__ float sinv;
    if ((tid & 31) == 0) sred[tid >> 5] = ss;
    __syncthreads();
    if (tid == 0) {
        float t = 0.f;
        #pragma unroll
        for (int i = 0; i < 8; i++) t += sred[i];
        sinv = rsqrtf(t / (float)HID + 1e-6f);
    }
    __syncthreads();
    float inv = sinv;
    const float4* wr = (const float4*)w;
    float4 wa = wr[tid], wb = wr[tid + 256];
    float va[8] = { a.x*inv*wa.x, a.y*inv*wa.y, a.z*inv*wa.z, a.w*inv*wa.w,
                    b.x*inv*wb.x, b.y*inv*wb.y, b.z*inv*wb.z, b.w*inv*wb.w };
    size_t base0 = (size_t)row * HID + tid*4;
    size_t base1 = (size_t)row * HID + (tid+256)*4;
    #pragma unroll
    for (int i = 0; i < 4; i++) {
        bf16 h0 = __float2bfloat16(va[i]);
        ohi[base0+i] = h0;
        olo[base0+i] = __float2bfloat16(va[i] - __bfloat162float(h0));
        bf16 h1 = __float2bfloat16(va[4+i]);
        ohi[base1+i] = h1;
        olo[base1+i] = __float2bfloat16(va[4+i] - __bfloat162float(h1));
    }
}

// ---------------------------------------------------------------------------
// split fp32 -> bf16 hi/lo (validated)
// ---------------------------------------------------------------------------
__global__ void split_kernel(const float* __restrict__ in, bf16* __restrict__ hi,
                             bf16* __restrict__ lo, int n4) {
    int i = blockIdx.x * 256 + threadIdx.x;
    if (i >= n4) return;
    float4 v = ((const float4*)in)[i];
    bf16 h0 = __float2bfloat16(v.x), h1 = __float2bfloat16(v.y);
    bf16 h2 = __float2bfloat16(v.z), h3 = __float2bfloat16(v.w);
    __nv_bfloat162 hh0; hh0.x = h0; hh0.y = h1;
    __nv_bfloat162 hh1; hh1.x = h2; hh1.y = h3;
    __nv_bfloat162 ll0, ll1;
    ll0.x = __float2bfloat16(v.x - __bfloat162float(h0));
    ll0.y = __float2bfloat16(v.y - __bfloat162float(h1));
    ll1.x = __float2bfloat16(v.z - __bfloat162float(h2));
    ll1.y = __float2bfloat16(v.w - __bfloat162float(h3));
    ((__nv_bfloat162*)hi)[i*2+0] = hh0;
    ((__nv_bfloat162*)hi)[i*2+1] = hh1;
    ((__nv_bfloat162*)lo)[i*2+0] = ll0;
    ((__nv_bfloat162*)lo)[i*2+1] = ll1;
}

// ---------------------------------------------------------------------------
// HMMA GEMM (NT): 256 threads, ldmatrix fragment loads (validated R10).
// Optional transposed V^T hi/lo epilogue (for the V projection).
// ---------------------------------------------------------------------------
__global__ __launch_bounds__(256, 1)
void gemm_mma(const bf16* __restrict__ Ah, const bf16* __restrict__ Al,
              const bf16* __restrict__ Bh, const bf16* __restrict__ Bl,
              const float* __restrict__ bias, float* __restrict__ Cf,
              bf16* __restrict__ Vth, bf16* __restrict__ Vtl, int N) {
    extern __shared__ __align__(128) char sm[];
    uint32_t sb = smem_u32(sm);
    int tid = threadIdx.x;
    int w = tid >> 5, lane = tid & 31, g = lane >> 2, tig = lane & 3;
    int wm = w & 1, wn = w >> 1;
    int brow = blockIdx.y * 128, bcol = blockIdx.x * 128;

    float acc[4][4][4];
    #pragma unroll
    for (int a = 0; a < 4; a++)
        #pragma unroll
        for (int b = 0; b < 4; b++)
            #pragma unroll
            for (int c = 0; c < 4; c++) acc[a][b][c] = 0.f;

    auto load_stage = [&](int s, int ck) {
        #pragma unroll
        for (int mat = 0; mat < 4; mat++) {
            const bf16* base = (mat == 0) ? Ah : (mat == 1) ? Al : (mat == 2) ? Bh : Bl;
            int ro = (mat < 2) ? brow : bcol;
            #pragma unroll
            for (int i = 0; i < 4; i++) {
                int id = i*256 + tid;
                int r = id >> 3, c = id & 7;
                cp16(sb + s*65536 + mat*16384 + r*128 + (((uint32_t)c*16) ^ ((uint32_t)(r&7)*16)),
                     base + (size_t)(ro + r)*2048 + ck*64 + c*8);
            }
        }
    };

    uint32_t lswz = (uint32_t)(lane & 7) * 16;
    uint32_t a_row = (uint32_t)(lane & 15);
    uint32_t a_kb  = (lane & 16) ? 16u : 0u;
    uint32_t b_row = (uint32_t)((lane & 16) ? 8 : 0) + (lane & 7);
    uint32_t b_kb  = (lane & 8) ? 16u : 0u;

    load_stage(0, 0);
    CP_COMMIT();

    for (int ck = 0; ck < 32; ck++) {
        if (ck + 1 < 32) { load_stage((ck+1)&1, ck+1); CP_COMMIT(); CP_WAIT(1); }
        else             { CP_WAIT(0); }
        __syncthreads();
        uint32_t tb = sb + (ck&1)*65536;
        #pragma unroll
        for (int ks = 0; ks < 4; ks++) {
            uint32_t ksb = (uint32_t)(32*ks);
            uint32_t ah[4][4], al[4][4];
            #pragma unroll
            for (int mb = 0; mb < 4; mb++) {
                uint32_t r = (uint32_t)(wm*64 + mb*16) + a_row;
                uint32_t addr = tb + r*128 + ((ksb + a_kb) ^ lswz);
                ldsm_x4(ah[mb][0], ah[mb][1], ah[mb][2], ah[mb][3], addr);
                ldsm_x4(al[mb][0], al[mb][1], al[mb][2], al[mb][3], addr + 16384);
            }
            uint32_t bh[4][2], bl[4][2];
            #pragma unroll
            for (int pr = 0; pr < 2; pr++) {
                uint32_t r = (uint32_t)(wn*32 + pr*16) + b_row;
                uint32_t addr = tb + 2*16384 + r*128 + ((ksb + b_kb) ^ lswz);
                ldsm_x4(bh[pr*2][0], bh[pr*2][1], bh[pr*2+1][0], bh[pr*2+1][1], addr);
                ldsm_x4(bl[pr*2][0], bl[pr*2][1], bl[pr*2+1][0], bl[pr*2+1][1], addr + 16384);
            }
            #pragma unroll
            for (int mb = 0; mb < 4; mb++)
                #pragma unroll
                for (int nb = 0; nb < 4; nb++) {
                    mma16816(acc[mb][nb], ah[mb], bh[nb]);
                    mma16816(acc[mb][nb], ah[mb], bl[nb]);
                    mma16816(acc[mb][nb], al[mb], bh[nb]);
                }
        }
        __syncthreads();
    }

    #pragma unroll
    for (int mb = 0; mb < 4; mb++) {
        #pragma unroll
        for (int half = 0; half < 2; half++) {
            int row = brow + wm*64 + mb*16 + g + 8*half;
            #pragma unroll
            for (int nb = 0; nb < 4; nb++) {
                int col = bcol + wn*32 + nb*8 + 2*tig;
                float v0 = acc[mb][nb][2*half];
                float v1 = acc[mb][nb][2*half+1];
                if (bias) { v0 += bias[col]; v1 += bias[col+1]; }
                if (Cf)
                    *(float2*)(Cf + (size_t)row * N + col) = make_float2(v0, v1);
                if (Vth) {
                    int bb = row >> 11, s = row & 2047;
                    int hk = col >> 7, d = col & 127;
                    size_t idx = (((size_t)bb*HKV + hk)*128 + d)*SS + s;
                    bf16 h0 = __float2bfloat16(v0);
                    bf16 h1 = __float2bfloat16(v1);
                    Vth[idx]      = h0;
                    Vtl[idx]      = __float2bfloat16(v0 - __bfloat162float(h0));
                    Vth[idx + SS] = h1;
                    Vtl[idx + SS] = __float2bfloat16(v1 - __bfloat162float(h1));
                }
            }
        }
    }
}

// ---------------------------------------------------------------------------
// RoPE: fp32 in -> bf16 hi/lo out (validated)
// ---------------------------------------------------------------------------
__global__ void rope_split_kernel(const float* __restrict__ t,
                                  bf16* __restrict__ oh, bf16* __restrict__ ol,
                                  int nHeads, int total) {
    int idx = blockIdx.x * blockDim.x + threadIdx.x;
    if (idx >= total) return;
    int j = idx & 63;
    int h = (idx >> 6) % nHeads;
    int s = (idx / (64 * nHeads)) % SS;
    int b = idx / (64 * nHeads * SS);
    float inv_freq = expf(-((float)(2*j) / 128.f) * logf(10000.f));
    float ang = (float)s * inv_freq;
    float c, sn;
    sincosf(ang, &sn, &c);
    size_t base = ((size_t)(b*SS + s) * nHeads + h) * 128;
    float a0 = t[base + j];
    float a1 = t[base + j + 64];
    float r0 = a0 * c - a1 * sn;
    float r1 = a1 * c + a0 * sn;
    bf16 h0 = __float2bfloat16(r0);
    oh[base + j] = h0;
    ol[base + j] = __float2bfloat16(r0 - __bfloat162float(h0));
    bf16 h1 = __float2bfloat16(r1);
    oh[base + j + 64] = h1;
    ol[base + j + 64] = __float2bfloat16(r1 - __bfloat162float(h1));
}

// ---------------------------------------------------------------------------
// Attention: HMMA S (ldmatrix frags) + register softmax + HMMA PV.
// 128 threads, BM=64, BN=64, D=128.
// smem (115712 B):
//   [0]      Qh/Ql  2x16KB : [d-half][64 rows][128B]  (dedicated, never overwritten)
//   [32768]  Kh/Kl  2x16KB : [d-half][64 keys][128B]
//   [65536]  Vth/Vtl 2x16KB: [d-half][64 d-rows][128B keys]
//   [98304]  Ps fp32: 64 q-rows x 68 floats (272B stride)
// ---------------------------------------------------------------------------
#define KH_OFF 32768
#define VT_OFF 65536
#define PS_OFF 98304
#define ATTN_SMEM (98304 + 64*272)

__global__ __launch_bounds__(128)
void attn_smma(const bf16* __restrict__ qh, const bf16* __restrict__ ql,
               const bf16* __restrict__ kh, const bf16* __restrict__ kl,
               const bf16* __restrict__ vth, const bf16* __restrict__ vtl,
               bf16* __restrict__ oh, bf16* __restrict__ ol) {
    extern __shared__ __align__(128) char sm[];
    uint32_t sb = smem_u32(sm);
    int tid = threadIdx.x, w = tid >> 5, lane = tid & 31, g = lane >> 2, tig = lane & 3;
    int qt = gridDim.x - 1 - blockIdx.x;
    int hq = blockIdx.y, b = blockIdx.z, gkv = hq >> 2;
    int q0 = qt * 64;
    int row0 = w*16 + g, row1 = row0 + 8;

    uint32_t lswz = (uint32_t)(lane & 7) * 16;
    uint32_t a_row = (uint32_t)(lane & 15);
    uint32_t a_kb  = (lane & 16) ? 16u : 0u;
    uint32_t b_row = (uint32_t)((lane & 16) ? 8 : 0) + (lane & 7);
    uint32_t b_kb  = (lane & 8) ? 16u : 0u;

    // ---- stage Q hi/lo into dedicated regions ----
    #pragma unroll
    for (int mat = 0; mat < 2; mat++) {
        const bf16* src = mat ? ql : qh;
        #pragma unroll
        for (int i = 0; i < 8; i++) {
            int id = i*128 + tid;
            int r = id >> 4, c = id & 15;
            cp16(sb + mat*16384 + (c>>3)*8192 + r*128 + (((uint32_t)(c&7)*16) ^ ((uint32_t)(r&7)*16)),
                 src + ((size_t)((b*SS + q0 + r)*HQ + hq))*128 + c*8);
        }
    }
    CP_COMMIT(); CP_WAIT(0);
    __syncthreads();

    float oacc[16][4];
    #pragma unroll
    for (int nb = 0; nb < 16; nb++)
        #pragma unroll
        for (int c = 0; c < 4; c++) oacc[nb][c] = 0.f;
    float m0 = -INFINITY, m1 = -INFINITY, l0 = 0.f, l1 = 0.f;
    const float scale = 0.08838834764831845f;

    for (int kt = 0; kt <= qt; kt++) {
        int n0 = kt * 64;
        __syncthreads();
        // K hi/lo
        #pragma unroll
        for (int mat = 0; mat < 2; mat++) {
            const bf16* base = mat ? kl : kh;
            #pragma unroll
            for (int i = 0; i < 8; i++) {
                int id = i*128 + tid;
                int r = id >> 4, c = id & 15;
                cp16(sb + KH_OFF + mat*16384 + (c>>3)*8192 + r*128 + (((uint32_t)(c&7)*16) ^ ((uint32_t)(r&7)*16)),
                     base + ((size_t)((b*SS + n0 + r)*HKV + gkv))*128 + c*8);
            }
        }
        // V^T hi/lo: 128 d-rows x 128B (64 keys)
        #pragma unroll
        for (int mat = 0; mat < 2; mat++) {
            const bf16* base = mat ? vtl : vth;
            #pragma unroll
            for (int i = 0; i < 8; i++) {
                int id = i*128 + tid;
                int r = id >> 3, c = id & 7;
                cp16(sb + VT_OFF + mat*16384 + (r>>6)*8192 + (r&63)*128 + (((uint32_t)c*16) ^ ((uint32_t)(r&7)*16)),
                     base + ((size_t)((b*HKV + gkv)*128 + r))*SS + n0 + c*8);
            }
        }
        CP_COMMIT(); CP_WAIT(0);
        __syncthreads();

        // ---- S = Q K^T (3-term, ldmatrix frags) ----
        float sacc[8][4];
        #pragma unroll
        for (int nb = 0; nb < 8; nb++)
            #pragma unroll
            for (int c = 0; c < 4; c++) sacc[nb][c] = 0.f;
        #pragma unroll
        for (int kb = 0; kb < 8; kb++) {
            uint32_t half = (uint32_t)(kb>>2)*8192;
            uint32_t ksb = (uint32_t)((kb&3)*32);
            uint32_t qhf[4], qlf[4];
            {
                uint32_t addr = sb + half + ((uint32_t)(w*16) + a_row)*128 + ((ksb + a_kb) ^ lswz);
                ldsm_x4(qhf[0], qhf[1], qhf[2], qhf[3], addr);
                ldsm_x4(qlf[0], qlf[1], qlf[2], qlf[3], addr + 16384);
            }
            uint32_t bh[8][2], bl[8][2];
            #pragma unroll
            for (int pr = 0; pr < 4; pr++) {
                uint32_t addr = sb + KH_OFF + half + ((uint32_t)(pr*16) + b_row)*128 + ((ksb + b_kb) ^ lswz);
                ldsm_x4(bh[pr*2][0], bh[pr*2][1], bh[pr*2+1][0], bh[pr*2+1][1], addr);
                ldsm_x4(bl[pr*2][0], bl[pr*2][1], bl[pr*2+1][0], bl[pr*2+1][1], addr + 16384);
            }
            #pragma unroll
            for (int nb = 0; nb < 8; nb++) {
                mma16816(sacc[nb], qhf, bh[nb]);
                mma16816(sacc[nb], qhf, bl[nb]);
                mma16816(sacc[nb], qlf, bh[nb]);
            }
        }

        // ---- online softmax (validated) ----
        #pragma unroll
        for (int nb = 0; nb < 8; nb++)
            #pragma unroll
            for (int c = 0; c < 4; c++) sacc[nb][c] *= scale;
        if (kt == qt) {
            #pragma unroll
            for (int nb = 0; nb < 8; nb++) {
                int col0 = nb*8 + 2*tig;
                if (col0     > row0) sacc[nb][0] = -INFINITY;
                if (col0 + 1 > row0) sacc[nb][1] = -INFINITY;
                if (col0     > row1) sacc[nb][2] = -INFINITY;
                if (col0 + 1 > row1) sacc[nb][3] = -INFINITY;
            }
        }
        float mx0 = -INFINITY, mx1 = -INFINITY;
        #pragma unroll
        for (int nb = 0; nb < 8; nb++) {
            mx0 = fmaxf(mx0, fmaxf(sacc[nb][0], sacc[nb][1]));
            mx1 = fmaxf(mx1, fmaxf(sacc[nb][2], sacc[nb][3]));
        }
        mx0 = fmaxf(mx0, __shfl_xor_sync(0xffffffffu, mx0, 1));
        mx0 = fmaxf(mx0, __shfl_xor_sync(0xffffffffu, mx0, 2));
        mx1 = fmaxf(mx1, __shfl_xor_sync(0xffffffffu, mx1, 1));
        mx1 = fmaxf(mx1, __shfl_xor_sync(0xffffffffu, mx1, 2));
        float mn0 = fmaxf(m0, mx0), mn1 = fmaxf(m1, mx1);
        float al0 = __expf(m0 - mn0), al1 = __expf(m1 - mn1);
        float rs0 = 0.f, rs1 = 0.f;
        #pragma unroll
        for (int nb = 0; nb < 8; nb++) {
            sacc[nb][0] = __expf(sacc[nb][0] - mn0); rs0 += sacc[nb][0];
            sacc[nb][1] = __expf(sacc[nb][1] - mn0); rs0 += sacc[nb][1];
            sacc[nb][2] = __expf(sacc[nb][2] - mn1); rs1 += sacc[nb][2];
            sacc[nb][3] = __expf(sacc[nb][3] - mn1); rs1 += sacc[nb][3];
        }
        rs0 += __shfl_xor_sync(0xffffffffu, rs0, 1);
        rs0 += __shfl_xor_sync(0xffffffffu, rs0, 2);
        rs1 += __shfl_xor_sync(0xffffffffu, rs1, 1);
        rs1 += __shfl_xor_sync(0xffffffffu, rs1, 2);
        l0 = l0*al0 + rs0; l1 = l1*al1 + rs1;
        m0 = mn0; m1 = mn1;
        #pragma unroll
        for (int nb = 0; nb < 16; nb++) {
            oacc[nb][0] *= al0; oacc[nb][1] *= al0;
            oacc[nb][2] *= al1; oacc[nb][3] *= al1;
        }

        // ---- P -> smem fp32 (validated storage) ----
        #pragma unroll
        for (int nb = 0; nb < 8; nb++) {
            uint32_t cb = (uint32_t)(nb*8 + 2*tig)*4;
            *(volatile float*)(sm + PS_OFF + (uint32_t)row0*272 + cb)     = sacc[nb][0];
            *(volatile float*)(sm + PS_OFF + (uint32_t)row0*272 + cb + 4) = sacc[nb][1];
            *(volatile float*)(sm + PS_OFF + (uint32_t)row1*272 + cb)     = sacc[nb][2];
            *(volatile float*)(sm + PS_OFF + (uint32_t)row1*272 + cb + 4) = sacc[nb][3];
        }
        __syncwarp();

        // ---- O += P V (3-term HMMA; A packed in-register from fp32 P) ----
        #pragma unroll
        for (int kb2 = 0; kb2 < 4; kb2++) {
            int k0 = kb2*16 + 2*tig;
            const volatile float* pr0 = (const volatile float*)(sm + PS_OFF + (uint32_t)row0*272);
            const volatile float* pr1 = (const volatile float*)(sm + PS_OFF + (uint32_t)row1*272);
            float p00 = pr0[k0], p01 = pr0[k0+1], p08 = pr0[k0+8], p09 = pr0[k0+9];
            float p10 = pr1[k0], p11 = pr1[k0+1], p18 = pr1[k0+8], p19 = pr1[k0+9];
            uint32_t aph[4], apl[4];
            aph[0] = packbf(p00, p01); aph[1] = packbf(p10, p11);
            aph[2] = packbf(p08, p09); aph[3] = packbf(p18, p19);
            __nv_bfloat162 t0, t1, t2, t3;
            memcpy(&t0, &aph[0], 4); memcpy(&t1, &aph[1], 4);
            memcpy(&t2, &aph[2], 4); memcpy(&t3, &aph[3], 4);
            apl[0] = packbf(p00 - __bfloat162float(t0.x), p01 - __bfloat162float(t0.y));
            apl[1] = packbf(p10 - __bfloat162float(t1.x), p11 - __bfloat162float(t1.y));
            apl[2] = packbf(p08 - __bfloat162float(t2.x), p09 - __bfloat162float(t2.y));
            apl[3] = packbf(p18 - __bfloat162float(t3.x), p19 - __bfloat162float(t3.y));

            uint32_t ksb2 = (uint32_t)(kb2*32);
            #pragma unroll
            for (int hv = 0; hv < 2; hv++) {
                #pragma unroll
                for (int pr = 0; pr < 4; pr++) {
                    uint32_t addr = sb + VT_OFF + (uint32_t)hv*8192
                                  + ((uint32_t)(pr*16) + b_row)*128 + ((ksb2 + b_kb) ^ lswz);
                    uint32_t bhA[2], bhB[2], blA[2], blB[2];
                    ldsm_x4(bhA[0], bhA[1], bhB[0], bhB[1], addr);
                    ldsm_x4(blA[0], blA[1], blB[0], blB[1], addr + 16384);
                    int nb = hv*8 + pr*2;
                    mma16816(oacc[nb],   aph, bhA);
                    mma16816(oacc[nb],   aph, blA);
                    mma16816(oacc[nb],   apl, bhA);
                    mma16816(oacc[nb+1], aph, bhB);
                    mma16816(oacc[nb+1], aph, blB);
                    mma16816(oacc[nb+1], apl, bhB);
                }
            }
        }
    }

    // ---- epilogue: normalize, emit bf16 hi/lo ----
    float inv0 = 1.f / l0, inv1 = 1.f / l1;
    size_t rbase0 = ((size_t)((b*SS + q0 + row0)*HQ + hq))*128;
    size_t rbase1 = rbase0 + (size_t)8*HQ*128;
    #pragma unroll
    for (int nb = 0; nb < 16; nb++) {
        int col = nb*8 + 2*tig;
        float v0 = oacc[nb][0]*inv0, v1 = oacc[nb][1]*inv0;
        float v2 = oacc[nb][2]*inv1, v3 = oacc[nb][3]*inv1;
        bf16 h0 = __float2bfloat16(v0), h1 = __float2bfloat16(v1);
        bf16 h2 = __float2bfloat16(v2), h3 = __float2bfloat16(v3);
        __nv_bfloat162 hh0; hh0.x = h0; hh0.y = h1;
        __nv_bfloat162 hh1; hh1.x = h2; hh1.y = h3;
        __nv_bfloat162 ll0, ll1;
        ll0.x = __float2bfloat16(v0 - __bfloat162float(h0));
        ll0.y = __float2bfloat16(v1 - __bfloat162float(h1));
        ll1.x = __float2bfloat16(v2 - __bfloat162float(h2));
        ll1.y = __float2bfloat16(v3 - __bfloat162float(h3));
        *(__nv_bfloat162*)(oh + rbase0 + col) = hh0;
        *(__nv_bfloat162*)(ol + rbase0 + col) = ll0;
        *(__nv_bfloat162*)(oh + rbase1 + col) = hh1;
        *(__nv_bfloat162*)(ol + rbase1 + col) = ll1;
    }
}

// ---------------------------------------------------------------------------
extern "C" void kernel_launch(void* const* d_in, const int* in_sizes, int n_in,
                              void* d_out, int out_size) {
    const float* x  = (const float*)d_in[0];
    const float* qp = (const float*)d_in[1];
    const float* kp = (const float*)d_in[2];
    const float* vp = (const float*)d_in[3];
    const float* qb = (const float*)d_in[4];
    const float* kb = (const float*)d_in[5];
    const float* vb = (const float*)d_in[6];
    const float* op = (const float*)d_in[7];
    const float* lw = (const float*)d_in[8];
    float* out = (float*)d_out;

    bf16 *hhi, *hlo, *wqh, *wql, *wkh, *wkl, *wvh, *wvl, *woh, *wol;
    bf16 *qhp, *qlp, *khp, *klp, *vth, *vtl, *athi, *atlo;
    float *q, *k;
    cudaGetSymbolAddress((void**)&hhi, g_h_hi);
    cudaGetSymbolAddress((void**)&hlo, g_h_lo);
    cudaGetSymbolAddress((void**)&wqh, g_wq_hi);
    cudaGetSymbolAddress((void**)&wql, g_wq_lo);
    cudaGetSymbolAddress((void**)&wkh, g_wk_hi);
    cudaGetSymbolAddress((void**)&wkl, g_wk_lo);
    cudaGetSymbolAddress((void**)&wvh, g_wv_hi);
    cudaGetSymbolAddress((void**)&wvl, g_wv_lo);
    cudaGetSymbolAddress((void**)&woh, g_wo_hi);
    cudaGetSymbolAddress((void**)&wol, g_wo_lo);
    cudaGetSymbolAddress((void**)&qhp, g_qh);
    cudaGetSymbolAddress((void**)&qlp, g_ql);
    cudaGetSymbolAddress((void**)&khp, g_kh);
    cudaGetSymbolAddress((void**)&klp, g_kl);
    cudaGetSymbolAddress((void**)&vth, g_vth);
    cudaGetSymbolAddress((void**)&vtl, g_vtl);
    cudaGetSymbolAddress((void**)&athi, g_att_hi);
    cudaGetSymbolAddress((void**)&atlo, g_att_lo);
    cudaGetSymbolAddress((void**)&q, g_q);
    cudaGetSymbolAddress((void**)&k, g_k);

    cudaFuncSetAttribute(gemm_mma, cudaFuncAttributeMaxDynamicSharedMemorySize, 131072);
    cudaFuncSetAttribute(attn_smma, cudaFuncAttributeMaxDynamicSharedMemorySize, ATTN_SMEM);

    // 0. split weights (validated)
    split_kernel<<<(QDIM*HID/4 + 255)/256, 256>>>(qp, wqh, wql, QDIM*HID/4);
    split_kernel<<<(KVDIM*HID/4 + 255)/256, 256>>>(kp, wkh, wkl, KVDIM*HID/4);
    split_kernel<<<(KVDIM*HID/4 + 255)/256, 256>>>(vp, wvh, wvl, KVDIM*HID/4);
    split_kernel<<<(HID*QDIM/4 + 255)/256, 256>>>(op, woh, wol, HID*QDIM/4);

    // 1. RMSNorm -> hi/lo (validated)
    rmsnorm_kernel<<<MM, 256>>>(x, lw, hhi, hlo);

    // 2. projections; V emits V^T hi/lo directly
    {
        dim3 gq(QDIM/128, MM/128);
        gemm_mma<<<gq, 256, 131072>>>(hhi, hlo, wqh, wql, qb, q, nullptr, nullptr, QDIM);
        dim3 gkv(KVDIM/128, MM/128);
        gemm_mma<<<gkv, 256, 131072>>>(hhi, hlo, wkh, wkl, kb, k, nullptr, nullptr, KVDIM);
        gemm_mma<<<gkv, 256, 131072>>>(hhi, hlo, wvh, wvl, vb, nullptr, vth, vtl, KVDIM);
    }

    // 3. RoPE -> hi/lo
    {
        int totq = BB * SS * HQ * 64;
        rope_split_kernel<<<(totq + 255)/256, 256>>>(q, qhp, qlp, HQ, totq);
        int totk = BB * SS * HKV * 64;
        rope_split_kernel<<<(totk + 255)/256, 256>>>(k, khp, klp, HKV, totk);
    }

    // 4. attention: HMMA S + HMMA PV -> bf16 hi/lo
    {
        dim3 ga(SS/64, HQ, BB);
        attn_smma<<<ga, 128, ATTN_SMEM>>>(qhp, qlp, khp, klp, vth, vtl, athi, atlo);
    }

    // 5. O projection -> fp32 out
    {
        dim3 go(HID/128, MM/128);
        gemm_mma<<<go, 256, 131072>>>(athi, atlo, woh, wol, nullptr, out, nullptr, nullptr, HID);
    }
}